// round 9
// baseline (speedup 1.0000x reference)
#include <cuda_runtime.h>
#include <cstdint>
#include <math.h>

#define NN 50000
#define NF 256
#define NE 400000
#define NL 50000
#define E0 256
#define C1 512
#define E1 128
#define DC 64
#define FULLM 0xffffffffu

// ---------------- persistent scratch (device globals; no allocation) ----------------
__device__ float g_v0z[(size_t)NN * E0];
__device__ float g_v1h[(size_t)NN * C1];
__device__ float g_v1z[(size_t)NN * E1];
__device__ float g_vdec[(size_t)2 * NL * DC];
__device__ float g_adec[(size_t)NN * DC];
__device__ float g_y[NL];
__device__ unsigned g_mInp[NN * 8];
__device__ unsigned g_mHs0[NN * 8];
__device__ unsigned g_mZs0[NN * 8];
__device__ unsigned g_mHs1[NN * 16];
__device__ int g_deg[NN];
__device__ int g_cur[NN];
__device__ int g_start[NN + 1];
__device__ int g_slot[NE];
__device__ int2 g_cpair[NE];

// ---------------- packed fp32x2 helpers (bit-exact dual IEEE fp32) -----------------
#define FMA2(acc, a, b) \
    asm("fma.rn.f32x2 %0, %1, %2, %3;" : "=l"(acc) : "l"(a), "l"(b), "l"(acc))

__device__ __forceinline__ unsigned long long pack2(float lo, float hi) {
    unsigned long long r;
    asm("mov.b64 %0, {%1, %2};" : "=l"(r) : "r"(__float_as_int(lo)), "r"(__float_as_int(hi)));
    return r;
}
__device__ __forceinline__ void unpack2(unsigned long long v, float& lo, float& hi) {
    int a, b;
    asm("mov.b64 {%0, %1}, %2;" : "=r"(a), "=r"(b) : "l"(v));
    lo = __int_as_float(a); hi = __int_as_float(b);
}
__device__ __forceinline__ float bit2f(unsigned b) {
    return __uint_as_float((0u - b) & 0x3f800000u);
}

// ---------------- threefry2x32 (exact JAX rotation/key-injection schedule) ----------
__host__ __device__ __forceinline__ void tf2x32(unsigned k0, unsigned k1,
                                                unsigned x0, unsigned x1,
                                                unsigned& o0, unsigned& o1) {
    unsigned ks2 = k0 ^ k1 ^ 0x1BD11BDAu;
    x0 += k0; x1 += k1;
#define TF_ROT(v, s) (((v) << (s)) | ((v) >> (32 - (s))))
#define TF_RND(r) { x0 += x1; x1 = TF_ROT(x1, r); x1 ^= x0; }
    TF_RND(13) TF_RND(15) TF_RND(26) TF_RND(6)  x0 += k1;  x1 += ks2 + 1u;
    TF_RND(17) TF_RND(29) TF_RND(16) TF_RND(24) x0 += ks2; x1 += k0 + 2u;
    TF_RND(13) TF_RND(15) TF_RND(26) TF_RND(6)  x0 += k0;  x1 += k1 + 3u;
    TF_RND(17) TF_RND(29) TF_RND(16) TF_RND(24) x0 += k1;  x1 += ks2 + 4u;
    TF_RND(13) TF_RND(15) TF_RND(26) TF_RND(6)  x0 += ks2; x1 += k0 + 5u;
#undef TF_RND
#undef TF_ROT
    o0 = x0; o1 = x1;
}

// PARTITIONABLE threefry random_bits: bits(i) = o0^o1 of threefry(key, (0, i)).
__device__ __forceinline__ float tf_u(unsigned k0, unsigned k1, unsigned i) {
    unsigned o0, o1;
    tf2x32(k0, k1, 0u, i, o0, o1);
    unsigned b = o0 ^ o1;
    return __uint_as_float((b >> 9) | 0x3f800000u) - 1.0f;
}

// ---------------- CSR build -------------------------------------------------------
__global__ void k_count(const int* __restrict__ dst) {
    int e = blockIdx.x * 256 + threadIdx.x;
    if (e < NE) atomicAdd(&g_deg[dst[e]], 1);
}

__global__ void k_scan() {
    __shared__ int warp_sums[32];
    __shared__ int s_carry;
    int tid = threadIdx.x;
    int lane = tid & 31, wq = tid >> 5;
    if (tid == 0) s_carry = 0;
    __syncthreads();
    for (int base = 0; base < NN; base += 1024) {
        int idx = base + tid;
        int v = (idx < NN) ? g_deg[idx] : 0;
        int x = v;
        for (int o = 1; o < 32; o <<= 1) {
            int y = __shfl_up_sync(FULLM, x, o);
            if (lane >= o) x += y;
        }
        if (lane == 31) warp_sums[wq] = x;
        __syncthreads();
        if (wq == 0) {
            int t = warp_sums[lane];
            for (int o = 1; o < 32; o <<= 1) {
                int y = __shfl_up_sync(FULLM, t, o);
                if (lane >= o) t += y;
            }
            warp_sums[lane] = t;
        }
        __syncthreads();
        int incl = x + ((wq > 0) ? warp_sums[wq - 1] : 0);
        int excl = incl - v + s_carry;
        if (idx < NN) { g_start[idx] = excl; g_cur[idx] = excl; }
        __syncthreads();
        if (tid == 1023) s_carry += incl;
        __syncthreads();
    }
    if (tid == 0) g_start[NN] = s_carry;
}

__global__ void k_scatter(const int* __restrict__ dst) {
    int e = blockIdx.x * 256 + threadIdx.x;
    if (e < NE) {
        int p = atomicAdd(&g_cur[dst[e]], 1);
        g_slot[p] = e;
    }
}

__global__ void k_sortgather(const int* __restrict__ esrc, const float* __restrict__ ew) {
    int n = blockIdx.x * 256 + threadIdx.x;
    if (n >= NN) return;
    int b = g_start[n], e = g_start[n + 1];
    for (int i = b + 1; i < e; i++) {
        int key = g_slot[i];
        int j = i - 1;
        while (j >= b && g_slot[j] > key) { g_slot[j + 1] = g_slot[j]; j--; }
        g_slot[j + 1] = key;
    }
    for (int i = b; i < e; i++) {
        int eid = g_slot[i];
        g_cpair[i] = make_int2(esrc[eid], __float_as_int(ew[eid]));
    }
}

// ---------------- step kernels ----------------------------------------------------
__global__ void k_inp(const float* __restrict__ x, unsigned k0, unsigned k1) {
    unsigned i = blockIdx.x * 256u + threadIdx.x;
    float u = tf_u(k0, k1, i);
    int s = (u <= x[i]);
    unsigned w = __ballot_sync(FULLM, s);
    if ((threadIdx.x & 31) == 0) g_mInp[i >> 5] = w;
}

// h0 = propagate(inp); hs0 = poisson(h0, k2). warp per dst node.
__global__ void k_prop1(unsigned pk0, unsigned pk1) {
    int wid = (blockIdx.x * blockDim.x + threadIdx.x) >> 5;
    int lane = threadIdx.x & 31;
    if (wid >= NN) return;
    int b = g_start[wid], e = g_start[wid + 1];
    float acc[8] = {0.f, 0.f, 0.f, 0.f, 0.f, 0.f, 0.f, 0.f};
    for (int p = b; p < e; p++) {
        int2 pr = g_cpair[p];
        int src = pr.x;
        float w = __int_as_float(pr.y);
        unsigned mw = g_mInp[src * 8 + (lane & 7)];
#pragma unroll
        for (int j = 0; j < 8; j++) {
            unsigned wj = __shfl_sync(FULLM, mw, j);
            acc[j] += ((wj >> lane) & 1u) ? w : 0.0f;
        }
    }
    unsigned base = (unsigned)wid * 256u + (unsigned)lane;
    unsigned myword = 0u;
#pragma unroll
    for (int j = 0; j < 8; j++) {
        float u = tf_u(pk0, pk1, base + 32u * j);
        int s = (u <= acc[j]);
        unsigned bb = __ballot_sync(FULLM, s);
        if (lane == j) myword = bb;
    }
    if (lane < 8) g_mHs0[wid * 8 + lane] = myword;
}

// h1 = propagate([zs0, hs0]); v1h,hs1 = lif. warp per dst node.
__global__ void k_prop2(int first) {
    int wid = (blockIdx.x * blockDim.x + threadIdx.x) >> 5;
    int lane = threadIdx.x & 31;
    if (wid >= NN) return;
    int b = g_start[wid], e = g_start[wid + 1];
    float acc[16];
#pragma unroll
    for (int j = 0; j < 16; j++) acc[j] = 0.f;
    int lw = lane & 15;
    for (int p = b; p < e; p++) {
        int2 pr = g_cpair[p];
        int src = pr.x;
        float w = __int_as_float(pr.y);
        unsigned mw = (lw < 8) ? g_mZs0[src * 8 + lw] : g_mHs0[src * 8 + (lw - 8)];
#pragma unroll
        for (int j = 0; j < 16; j++) {
            unsigned wj = __shfl_sync(FULLM, mw, j);
            acc[j] += ((wj >> lane) & 1u) ? w : 0.0f;
        }
    }
    size_t vb = (size_t)wid * C1 + lane;
    unsigned myword = 0u;
#pragma unroll
    for (int j = 0; j < 16; j++) {
        float vv = first ? acc[j] : (g_v1h[vb + 32 * j] * 0.5f + acc[j]);
        int s = ((vv - 0.2f) >= 0.f);
        g_v1h[vb + 32 * j] = vv - (s ? 0.2f : 0.f);
        unsigned bb = __ballot_sync(FULLM, s);
        if (lane == j) myword = bb;
    }
    if (lane < 16) g_mHs1[wid * 16 + lane] = myword;
}

// spike-GEMM + LIF, 64-node tiles, 16 nodes x 4 cols per thread (bit-exact k order).
// threads = NO (TX = NO/4 col-threads x 4 node-groups of 16).
template <int K, int NO, int WPB, int OW, int KC>
__global__ void __launch_bounds__(NO) k_lifgemm(
        const unsigned* __restrict__ maskA, const float* __restrict__ W,
        float* __restrict__ v, unsigned* __restrict__ outMask, int first) {
    constexpr int TX = NO / 4;
    constexpr int NT = NO;
    __shared__ __align__(16) float sA[KC * 64];
    int tid = threadIdx.x;
    int tx = tid % TX;
    int ty = tid / TX;
    int lane = tid & 31;
    int node0 = blockIdx.x * 64;

    unsigned long long acc2[32];
#pragma unroll
    for (int q = 0; q < 32; q++) acc2[q] = 0ull;

    for (int k0 = 0; k0 < K; k0 += KC) {
        for (int m = tid; m < 64 * (KC / 32); m += NT) {
            int node = m & 63;
            int sub = m >> 6;
            int n = node0 + node;
            unsigned wbits = (n < NN) ? maskA[n * WPB + (k0 >> 5) + sub] : 0u;
            float* dst = sA + (sub * 32) * 64 + node;
#pragma unroll
            for (int bt = 0; bt < 32; bt++)
                dst[bt * 64] = bit2f((wbits >> bt) & 1u);
        }
        __syncthreads();
#pragma unroll 4
        for (int kk = 0; kk < KC; kk++) {
            const float* wrow = W + (size_t)(k0 + kk) * NO;
            unsigned long long w2[4];
#pragma unroll
            for (int j = 0; j < 4; j++) {
                float w = wrow[tx + TX * j];
                w2[j] = pack2(w, w);
            }
            const ulonglong2* ap = (const ulonglong2*)(sA + kk * 64 + ty * 16);
            ulonglong2 a01 = ap[0], a23 = ap[1], a45 = ap[2], a67 = ap[3];
            unsigned long long av[8] = {a01.x, a01.y, a23.x, a23.y,
                                        a45.x, a45.y, a67.x, a67.y};
#pragma unroll
            for (int p = 0; p < 8; p++)
#pragma unroll
                for (int j = 0; j < 4; j++)
                    FMA2(acc2[p * 4 + j], av[p], w2[j]);
        }
        __syncthreads();
    }

#pragma unroll
    for (int p = 0; p < 8; p++) {
        float aLo[4], aHi[4];
#pragma unroll
        for (int j = 0; j < 4; j++) unpack2(acc2[p * 4 + j], aLo[j], aHi[j]);
#pragma unroll
        for (int h = 0; h < 2; h++) {
            int n = node0 + ty * 16 + 2 * p + h;
#pragma unroll
            for (int j = 0; j < 4; j++) {
                int c = tx + TX * j;
                float a = h ? aHi[j] : aLo[j];
                int s = 0;
                if (n < NN) {
                    size_t idx = (size_t)n * NO + c;
                    float vv = first ? a : (v[idx] * 0.5f + a);
                    s = ((vv - 0.2f) >= 0.f);
                    v[idx] = vv - (s ? 0.2f : 0.f);
                }
                unsigned bb = __ballot_sync(FULLM, s);
                if (lane == 0 && n < NN) outMask[n * OW + (c >> 5)] = bb;
            }
        }
    }
}

// GEMM2 (64-node tiles) fused with decoder pre-activation.
__global__ void __launch_bounds__(128) k_gemm2dec(
        const float* __restrict__ W2, const float* __restrict__ Wd, int first) {
    constexpr int K = 512, NO = 128, TX = 32, NT = 128, KC = 128, WPB = 16;
    __shared__ __align__(16) float sA[KC * 64];
    __shared__ unsigned smask[64 * 4];
    int tid = threadIdx.x;
    int tx = tid % TX;
    int ty = tid / TX;
    int lane = tid & 31;
    int node0 = blockIdx.x * 64;

    unsigned long long acc2[32];
#pragma unroll
    for (int q = 0; q < 32; q++) acc2[q] = 0ull;

    for (int k0 = 0; k0 < K; k0 += KC) {
        for (int m = tid; m < 64 * (KC / 32); m += NT) {
            int node = m & 63;
            int sub = m >> 6;
            int n = node0 + node;
            unsigned wbits = (n < NN) ? g_mHs1[n * WPB + (k0 >> 5) + sub] : 0u;
            float* dst = sA + (sub * 32) * 64 + node;
#pragma unroll
            for (int bt = 0; bt < 32; bt++)
                dst[bt * 64] = bit2f((wbits >> bt) & 1u);
        }
        __syncthreads();
#pragma unroll 4
        for (int kk = 0; kk < KC; kk++) {
            const float* wrow = W2 + (size_t)(k0 + kk) * NO;
            unsigned long long w2[4];
#pragma unroll
            for (int j = 0; j < 4; j++) {
                float w = wrow[tx + TX * j];
                w2[j] = pack2(w, w);
            }
            const ulonglong2* ap = (const ulonglong2*)(sA + kk * 64 + ty * 16);
            ulonglong2 a01 = ap[0], a23 = ap[1], a45 = ap[2], a67 = ap[3];
            unsigned long long av[8] = {a01.x, a01.y, a23.x, a23.y,
                                        a45.x, a45.y, a67.x, a67.y};
#pragma unroll
            for (int p = 0; p < 8; p++)
#pragma unroll
                for (int j = 0; j < 4; j++)
                    FMA2(acc2[p * 4 + j], av[p], w2[j]);
        }
        __syncthreads();
    }

    // LIF epilogue -> zs1 mask words into smem
#pragma unroll
    for (int p = 0; p < 8; p++) {
        float aLo[4], aHi[4];
#pragma unroll
        for (int j = 0; j < 4; j++) unpack2(acc2[p * 4 + j], aLo[j], aHi[j]);
#pragma unroll
        for (int h = 0; h < 2; h++) {
            int node = ty * 16 + 2 * p + h;
            int n = node0 + node;
#pragma unroll
            for (int j = 0; j < 4; j++) {
                float a = h ? aHi[j] : aLo[j];
                int s = 0;
                if (n < NN) {
                    size_t idx = (size_t)n * E1 + tx + TX * j;
                    float vv = first ? a : (g_v1z[idx] * 0.5f + a);
                    s = ((vv - 0.2f) >= 0.f);
                    g_v1z[idx] = vv - (s ? 0.2f : 0.f);
                }
                unsigned bb = __ballot_sync(FULLM, s);
                if (lane == 0) smask[node * 4 + j] = bb;
            }
        }
    }
    __syncthreads();

    // decoder pre-activation: adec[n][col] = zs1[n] @ Wd[:,col]  (K=128, 64 cols)
    for (int m = tid; m < 256; m += NT) {
        int node = m & 63;
        int sub = m >> 6;
        unsigned wbits = smask[node * 4 + sub];
        float* dst = sA + (sub * 32) * 64 + node;
#pragma unroll
        for (int bt = 0; bt < 32; bt++)
            dst[bt * 64] = bit2f((wbits >> bt) & 1u);
    }
    __syncthreads();
    int col = tid % 64;
    int half = tid / 64;   // 0/1: nodes 0-31 / 32-63
#pragma unroll
    for (int q = 0; q < 16; q++) acc2[q] = 0ull;
#pragma unroll 4
    for (int kk = 0; kk < 128; kk++) {
        float w = Wd[kk * DC + col];
        unsigned long long w2 = pack2(w, w);
        const ulonglong2* a4 = (const ulonglong2*)(sA + kk * 64 + half * 32);
#pragma unroll
        for (int q = 0; q < 8; q++) {
            ulonglong2 a = a4[q];
            FMA2(acc2[2 * q + 0], a.x, w2);
            FMA2(acc2[2 * q + 1], a.y, w2);
        }
    }
#pragma unroll
    for (int i = 0; i < 32; i++) {
        float lo, hi;
        unpack2(acc2[i >> 1], lo, hi);
        float a = (i & 1) ? hi : lo;
        int n = node0 + half * 32 + i;
        if (n < NN) g_adec[(size_t)n * DC + col] = a;
    }
}

// decoder: gather adec; LIF; accumulate y; last step writes sigmoid(mean) to out.
__global__ void k_dec(const int* __restrict__ ns, const int* __restrict__ nt,
                      const float* __restrict__ bd, const float* __restrict__ wrec,
                      int first, int last, float* __restrict__ out) {
    int wid = (blockIdx.x * blockDim.x + threadIdx.x) >> 5;
    int lane = threadIdx.x & 31;
    if (wid >= NL) return;
    int sn = ns[wid], tn = nt[wid];
    float a0s = g_adec[(size_t)sn * DC + lane];
    float a1s = g_adec[(size_t)sn * DC + lane + 32];
    float a0t = g_adec[(size_t)tn * DC + lane];
    float a1t = g_adec[(size_t)tn * DC + lane + 32];
    float b0 = bd[lane], b1 = bd[lane + 32];
    size_t is0 = (size_t)wid * DC + lane;
    size_t it0 = (size_t)(wid + NL) * DC + lane;
    float vv;
    vv = (first ? 0.f : g_vdec[is0] * 0.5f) + (a0s + b0);
    int zs0b = ((vv - 0.2f) >= 0.f); g_vdec[is0] = vv - (zs0b ? 0.2f : 0.f);
    vv = (first ? 0.f : g_vdec[is0 + 32] * 0.5f) + (a1s + b1);
    int zs1b = ((vv - 0.2f) >= 0.f); g_vdec[is0 + 32] = vv - (zs1b ? 0.2f : 0.f);
    vv = (first ? 0.f : g_vdec[it0] * 0.5f) + (a0t + b0);
    int zt0b = ((vv - 0.2f) >= 0.f); g_vdec[it0] = vv - (zt0b ? 0.2f : 0.f);
    vv = (first ? 0.f : g_vdec[it0 + 32] * 0.5f) + (a1t + b1);
    int zt1b = ((vv - 0.2f) >= 0.f); g_vdec[it0 + 32] = vv - (zt1b ? 0.2f : 0.f);

    float yp = ((zs0b && zt0b) ? wrec[lane] : 0.f) + ((zs1b && zt1b) ? wrec[lane + 32] : 0.f);
#pragma unroll
    for (int off = 16; off; off >>= 1) yp += __shfl_down_sync(FULLM, yp, off);
    if (lane == 0) {
        float ytot = first ? yp : (g_y[wid] + yp);
        if (last) {
            float m = ytot * 0.25f;
            float r;
            if (m >= 0.f) { float z = expf(-m); r = 1.f / (1.f + z); }
            else          { float z = expf(m);  r = z / (1.f + z); }
            out[wid] = r;
        } else {
            g_y[wid] = ytot;
        }
    }
}

// ---------------- host ------------------------------------------------------------
extern "C" void kernel_launch(void* const* d_in, const int* in_sizes, int n_in,
                              void* d_out, int out_size) {
    const float* x    = (const float*)d_in[0];
    const float* W1   = (const float*)d_in[1];
    const float* W2   = (const float*)d_in[2];
    const float* Wd   = (const float*)d_in[3];
    const float* bd   = (const float*)d_in[4];
    const float* wrec = (const float*)d_in[5];
    const float* ew   = (const float*)d_in[6];
    const int* esrc   = (const int*)d_in[7];
    const int* edst   = (const int*)d_in[8];
    const int* ns     = (const int*)d_in[9];
    const int* nt     = (const int*)d_in[10];
    float* out = (float*)d_out;

    void* p;
    float *v0z;
    unsigned *mHs0, *mZs0;
    int* deg;
    cudaGetSymbolAddress(&p, g_v0z);  v0z  = (float*)p;
    cudaGetSymbolAddress(&p, g_deg);  deg  = (int*)p;
    cudaGetSymbolAddress(&p, g_mHs0); mHs0 = (unsigned*)p;
    cudaGetSymbolAddress(&p, g_mZs0); mZs0 = (unsigned*)p;

    cudaMemsetAsync(deg, 0, sizeof(int) * NN);

    k_count<<<(NE + 255) / 256, 256>>>(edst);
    k_scan<<<1, 1024>>>();
    k_scatter<<<(NE + 255) / 256, 256>>>(edst);
    k_sortgather<<<(NN + 255) / 256, 256>>>(esrc, ew);

    const int GB64 = (NN + 63) / 64;
    for (unsigned t = 0; t < 4; t++) {
        int first = (t == 0);
        int last = (t == 3);
        unsigned kt0, kt1, k1_0, k1_1, k2_0, k2_1;
        tf2x32(0u, 42u, 0u, t, kt0, kt1);
        tf2x32(kt0, kt1, 0u, 0u, k1_0, k1_1);   // k1 = split(kt)[0]
        tf2x32(kt0, kt1, 0u, 1u, k2_0, k2_1);   // k2 = split(kt)[1]

        k_inp<<<NN, 256>>>(x, k1_0, k1_1);
        k_prop1<<<(NN * 32) / 256, 256>>>(k2_0, k2_1);
        k_lifgemm<256, 256, 8, 8, 128><<<GB64, 256>>>(mHs0, W1, v0z, mZs0, first);
        k_prop2<<<(NN * 32) / 256, 256>>>(first);
        k_gemm2dec<<<GB64, 128>>>(W2, Wd, first);
        k_dec<<<(NL * 32) / 256, 256>>>(ns, nt, bd, wrec, first, last, out);
    }
}

// round 10
// speedup vs baseline: 1.1691x; 1.1691x over previous
#include <cuda_runtime.h>
#include <cstdint>
#include <math.h>

#define NN 50000
#define NF 256
#define NE 400000
#define NL 50000
#define E0 256
#define C1 512
#define E1 128
#define DC 64
#define FULLM 0xffffffffu

// ---------------- persistent scratch (device globals; no allocation) ----------------
__device__ float g_v0z[(size_t)NN * E0];
__device__ float g_v1h[(size_t)NN * C1];
__device__ float g_v1z[(size_t)NN * E1];
__device__ float g_vdec[(size_t)2 * NL * DC];
__device__ float g_adec[(size_t)NN * DC];
__device__ float g_y[NL];
__device__ unsigned g_mInp[NN * 8];
__device__ unsigned g_mHs0[NN * 8];
__device__ unsigned g_mZs0[NN * 8];
__device__ unsigned g_mHs1[NN * 16];
__device__ int g_deg[NN];
__device__ int g_cur[NN];
__device__ int g_start[NN + 1];
__device__ int g_slot[NE];
__device__ int2 g_cpair[NE];

// ---------------- packed fp32x2 helpers (bit-exact dual IEEE fp32) -----------------
#define FMA2(acc, a, b) \
    asm("fma.rn.f32x2 %0, %1, %2, %3;" : "=l"(acc) : "l"(a), "l"(b), "l"(acc))

__device__ __forceinline__ unsigned long long pack2(float lo, float hi) {
    unsigned long long r;
    asm("mov.b64 %0, {%1, %2};" : "=l"(r) : "r"(__float_as_int(lo)), "r"(__float_as_int(hi)));
    return r;
}
__device__ __forceinline__ void unpack2(unsigned long long v, float& lo, float& hi) {
    int a, b;
    asm("mov.b64 {%0, %1}, %2;" : "=r"(a), "=r"(b) : "l"(v));
    lo = __int_as_float(a); hi = __int_as_float(b);
}
__device__ __forceinline__ float bit2f(unsigned b) {
    return __uint_as_float((0u - b) & 0x3f800000u);
}

// ---------------- threefry2x32 (exact JAX rotation/key-injection schedule) ----------
__host__ __device__ __forceinline__ void tf2x32(unsigned k0, unsigned k1,
                                                unsigned x0, unsigned x1,
                                                unsigned& o0, unsigned& o1) {
    unsigned ks2 = k0 ^ k1 ^ 0x1BD11BDAu;
    x0 += k0; x1 += k1;
#define TF_ROT(v, s) (((v) << (s)) | ((v) >> (32 - (s))))
#define TF_RND(r) { x0 += x1; x1 = TF_ROT(x1, r); x1 ^= x0; }
    TF_RND(13) TF_RND(15) TF_RND(26) TF_RND(6)  x0 += k1;  x1 += ks2 + 1u;
    TF_RND(17) TF_RND(29) TF_RND(16) TF_RND(24) x0 += ks2; x1 += k0 + 2u;
    TF_RND(13) TF_RND(15) TF_RND(26) TF_RND(6)  x0 += k0;  x1 += k1 + 3u;
    TF_RND(17) TF_RND(29) TF_RND(16) TF_RND(24) x0 += k1;  x1 += ks2 + 4u;
    TF_RND(13) TF_RND(15) TF_RND(26) TF_RND(6)  x0 += ks2; x1 += k0 + 5u;
#undef TF_RND
#undef TF_ROT
    o0 = x0; o1 = x1;
}

// PARTITIONABLE threefry random_bits: bits(i) = o0^o1 of threefry(key, (0, i)).
__device__ __forceinline__ float tf_u(unsigned k0, unsigned k1, unsigned i) {
    unsigned o0, o1;
    tf2x32(k0, k1, 0u, i, o0, o1);
    unsigned b = o0 ^ o1;
    return __uint_as_float((b >> 9) | 0x3f800000u) - 1.0f;
}

// ---------------- CSR build -------------------------------------------------------
__global__ void k_count(const int* __restrict__ dst) {
    int e = blockIdx.x * 256 + threadIdx.x;
    if (e < NE) atomicAdd(&g_deg[dst[e]], 1);
}

__global__ void k_scan() {
    __shared__ int warp_sums[32];
    __shared__ int s_carry;
    int tid = threadIdx.x;
    int lane = tid & 31, wq = tid >> 5;
    if (tid == 0) s_carry = 0;
    __syncthreads();
    for (int base = 0; base < NN; base += 1024) {
        int idx = base + tid;
        int v = (idx < NN) ? g_deg[idx] : 0;
        int x = v;
        for (int o = 1; o < 32; o <<= 1) {
            int y = __shfl_up_sync(FULLM, x, o);
            if (lane >= o) x += y;
        }
        if (lane == 31) warp_sums[wq] = x;
        __syncthreads();
        if (wq == 0) {
            int t = warp_sums[lane];
            for (int o = 1; o < 32; o <<= 1) {
                int y = __shfl_up_sync(FULLM, t, o);
                if (lane >= o) t += y;
            }
            warp_sums[lane] = t;
        }
        __syncthreads();
        int incl = x + ((wq > 0) ? warp_sums[wq - 1] : 0);
        int excl = incl - v + s_carry;
        if (idx < NN) { g_start[idx] = excl; g_cur[idx] = excl; }
        __syncthreads();
        if (tid == 1023) s_carry += incl;
        __syncthreads();
    }
    if (tid == 0) g_start[NN] = s_carry;
}

__global__ void k_scatter(const int* __restrict__ dst) {
    int e = blockIdx.x * 256 + threadIdx.x;
    if (e < NE) {
        int p = atomicAdd(&g_cur[dst[e]], 1);
        g_slot[p] = e;
    }
}

__global__ void k_sortgather(const int* __restrict__ esrc, const float* __restrict__ ew) {
    int n = blockIdx.x * 256 + threadIdx.x;
    if (n >= NN) return;
    int b = g_start[n], e = g_start[n + 1];
    for (int i = b + 1; i < e; i++) {
        int key = g_slot[i];
        int j = i - 1;
        while (j >= b && g_slot[j] > key) { g_slot[j + 1] = g_slot[j]; j--; }
        g_slot[j + 1] = key;
    }
    for (int i = b; i < e; i++) {
        int eid = g_slot[i];
        g_cpair[i] = make_int2(esrc[eid], __float_as_int(ew[eid]));
    }
}

// ---------------- step kernels ----------------------------------------------------
__global__ void k_inp(const float* __restrict__ x, unsigned k0, unsigned k1) {
    unsigned i = blockIdx.x * 256u + threadIdx.x;
    float u = tf_u(k0, k1, i);
    int s = (u <= x[i]);
    unsigned w = __ballot_sync(FULLM, s);
    if ((threadIdx.x & 31) == 0) g_mInp[i >> 5] = w;
}

// h0 = propagate(inp); hs0 = poisson(h0, k2). warp per dst node.
__global__ void k_prop1(unsigned pk0, unsigned pk1) {
    int wid = (blockIdx.x * blockDim.x + threadIdx.x) >> 5;
    int lane = threadIdx.x & 31;
    if (wid >= NN) return;
    int b = g_start[wid], e = g_start[wid + 1];
    float acc[8] = {0.f, 0.f, 0.f, 0.f, 0.f, 0.f, 0.f, 0.f};
    for (int p = b; p < e; p++) {
        int2 pr = g_cpair[p];
        int src = pr.x;
        float w = __int_as_float(pr.y);
        unsigned mw = g_mInp[src * 8 + (lane & 7)];
#pragma unroll
        for (int j = 0; j < 8; j++) {
            unsigned wj = __shfl_sync(FULLM, mw, j);
            acc[j] += ((wj >> lane) & 1u) ? w : 0.0f;
        }
    }
    unsigned base = (unsigned)wid * 256u + (unsigned)lane;
    unsigned myword = 0u;
#pragma unroll
    for (int j = 0; j < 8; j++) {
        float u = tf_u(pk0, pk1, base + 32u * j);
        int s = (u <= acc[j]);
        unsigned bb = __ballot_sync(FULLM, s);
        if (lane == j) myword = bb;
    }
    if (lane < 8) g_mHs0[wid * 8 + lane] = myword;
}

// h1 = propagate([zs0, hs0]); v1h,hs1 = lif. warp per dst node.
__global__ void k_prop2(int first) {
    int wid = (blockIdx.x * blockDim.x + threadIdx.x) >> 5;
    int lane = threadIdx.x & 31;
    if (wid >= NN) return;
    int b = g_start[wid], e = g_start[wid + 1];
    float acc[16];
#pragma unroll
    for (int j = 0; j < 16; j++) acc[j] = 0.f;
    int lw = lane & 15;
    for (int p = b; p < e; p++) {
        int2 pr = g_cpair[p];
        int src = pr.x;
        float w = __int_as_float(pr.y);
        unsigned mw = (lw < 8) ? g_mZs0[src * 8 + lw] : g_mHs0[src * 8 + (lw - 8)];
#pragma unroll
        for (int j = 0; j < 16; j++) {
            unsigned wj = __shfl_sync(FULLM, mw, j);
            acc[j] += ((wj >> lane) & 1u) ? w : 0.0f;
        }
    }
    size_t vb = (size_t)wid * C1 + lane;
    unsigned myword = 0u;
#pragma unroll
    for (int j = 0; j < 16; j++) {
        float vv = first ? acc[j] : (g_v1h[vb + 32 * j] * 0.5f + acc[j]);
        int s = ((vv - 0.2f) >= 0.f);
        g_v1h[vb + 32 * j] = vv - (s ? 0.2f : 0.f);
        unsigned bb = __ballot_sync(FULLM, s);
        if (lane == j) myword = bb;
    }
    if (lane < 16) g_mHs1[wid * 16 + lane] = myword;
}

// spike-GEMM + LIF, 32-node tiles, 16 nodes x 4 cols per thread (bit-exact k order).
template <int K, int NO, int WPB, int OW, int KC>
__global__ void __launch_bounds__((NO / 4) * 2) k_lifgemm(
        const unsigned* __restrict__ maskA, const float* __restrict__ W,
        float* __restrict__ v, unsigned* __restrict__ outMask, int first) {
    constexpr int TX = NO / 4;
    constexpr int NT = TX * 2;
    __shared__ __align__(16) float sA[KC * 32];
    int tid = threadIdx.x;
    int tx = tid % TX;
    int ty = tid / TX;
    int lane = tid & 31;
    int node0 = blockIdx.x * 32;

    unsigned long long acc2[32];
#pragma unroll
    for (int q = 0; q < 32; q++) acc2[q] = 0ull;

    for (int k0 = 0; k0 < K; k0 += KC) {
        for (int m = tid; m < KC; m += NT) {
            int node = m & 31;
            int sub = m >> 5;
            int n = node0 + node;
            unsigned wbits = (n < NN) ? maskA[n * WPB + (k0 >> 5) + sub] : 0u;
            float* dst = sA + (sub * 32) * 32 + node;
#pragma unroll
            for (int bt = 0; bt < 32; bt++)
                dst[bt * 32] = bit2f((wbits >> bt) & 1u);
        }
        __syncthreads();
#pragma unroll 4
        for (int kk = 0; kk < KC; kk++) {
            const float* wrow = W + (size_t)(k0 + kk) * NO;
            unsigned long long w2[4];
#pragma unroll
            for (int j = 0; j < 4; j++) {
                float w = wrow[tx + TX * j];
                w2[j] = pack2(w, w);
            }
            const ulonglong2* ap = (const ulonglong2*)(sA + kk * 32 + ty * 16);
            ulonglong2 a01 = ap[0], a23 = ap[1], a45 = ap[2], a67 = ap[3];
            unsigned long long av[8] = {a01.x, a01.y, a23.x, a23.y,
                                        a45.x, a45.y, a67.x, a67.y};
#pragma unroll
            for (int p = 0; p < 8; p++)
#pragma unroll
                for (int j = 0; j < 4; j++)
                    FMA2(acc2[p * 4 + j], av[p], w2[j]);
        }
        __syncthreads();
    }

#pragma unroll
    for (int p = 0; p < 8; p++) {
        float aLo[4], aHi[4];
#pragma unroll
        for (int j = 0; j < 4; j++) unpack2(acc2[p * 4 + j], aLo[j], aHi[j]);
#pragma unroll
        for (int h = 0; h < 2; h++) {
            int n = node0 + ty * 16 + 2 * p + h;
            if (n >= NN) continue;
#pragma unroll
            for (int j = 0; j < 4; j++) {
                int c = tx + TX * j;
                float a = h ? aHi[j] : aLo[j];
                size_t idx = (size_t)n * NO + c;
                float vv = first ? a : (v[idx] * 0.5f + a);
                int s = ((vv - 0.2f) >= 0.f);
                v[idx] = vv - (s ? 0.2f : 0.f);
                unsigned bb = __ballot_sync(FULLM, s);
                if (lane == 0) outMask[n * OW + (c >> 5)] = bb;
            }
        }
    }
}

// GEMM2 fused with decoder pre-activation (32-node tiles, 64 threads).
__global__ void __launch_bounds__(64) k_gemm2dec(
        const float* __restrict__ W2, const float* __restrict__ Wd, int first) {
    constexpr int K = 512, NO = 128, TX = 32, NT = 64, KC = 256, WPB = 16;
    __shared__ __align__(16) float sA[KC * 32];
    __shared__ unsigned smask[32 * 4];
    int tid = threadIdx.x;
    int tx = tid % TX;
    int ty = tid / TX;
    int lane = tid & 31;
    int node0 = blockIdx.x * 32;

    unsigned long long acc2[32];
#pragma unroll
    for (int q = 0; q < 32; q++) acc2[q] = 0ull;

    for (int k0 = 0; k0 < K; k0 += KC) {
        for (int m = tid; m < KC; m += NT) {
            int node = m & 31;
            int sub = m >> 5;
            int n = node0 + node;
            unsigned wbits = (n < NN) ? g_mHs1[n * WPB + (k0 >> 5) + sub] : 0u;
            float* dst = sA + (sub * 32) * 32 + node;
#pragma unroll
            for (int bt = 0; bt < 32; bt++)
                dst[bt * 32] = bit2f((wbits >> bt) & 1u);
        }
        __syncthreads();
#pragma unroll 4
        for (int kk = 0; kk < KC; kk++) {
            const float* wrow = W2 + (size_t)(k0 + kk) * NO;
            unsigned long long w2[4];
#pragma unroll
            for (int j = 0; j < 4; j++) {
                float w = wrow[tx + TX * j];
                w2[j] = pack2(w, w);
            }
            const ulonglong2* ap = (const ulonglong2*)(sA + kk * 32 + ty * 16);
            ulonglong2 a01 = ap[0], a23 = ap[1], a45 = ap[2], a67 = ap[3];
            unsigned long long av[8] = {a01.x, a01.y, a23.x, a23.y,
                                        a45.x, a45.y, a67.x, a67.y};
#pragma unroll
            for (int p = 0; p < 8; p++)
#pragma unroll
                for (int j = 0; j < 4; j++)
                    FMA2(acc2[p * 4 + j], av[p], w2[j]);
        }
        __syncthreads();
    }

    // LIF epilogue -> zs1 mask words into smem
#pragma unroll
    for (int p = 0; p < 8; p++) {
        float aLo[4], aHi[4];
#pragma unroll
        for (int j = 0; j < 4; j++) unpack2(acc2[p * 4 + j], aLo[j], aHi[j]);
#pragma unroll
        for (int h = 0; h < 2; h++) {
            int node = ty * 16 + 2 * p + h;
            int n = node0 + node;
#pragma unroll
            for (int j = 0; j < 4; j++) {
                float a = h ? aHi[j] : aLo[j];
                int s = 0;
                if (n < NN) {
                    size_t idx = (size_t)n * E1 + tx + TX * j;
                    float vv = first ? a : (g_v1z[idx] * 0.5f + a);
                    s = ((vv - 0.2f) >= 0.f);
                    g_v1z[idx] = vv - (s ? 0.2f : 0.f);
                }
                unsigned bb = __ballot_sync(FULLM, s);
                if (lane == 0) smask[node * 4 + j] = bb;
            }
        }
    }
    __syncthreads();

    // decoder pre-activation: adec[n][col] = zs1[n] @ Wd[:,col]
    for (int m = tid; m < 128; m += 64) {
        int node = m & 31;
        int sub = m >> 5;
        unsigned wbits = smask[node * 4 + sub];
        float* dst = sA + (sub * 32) * 32 + node;
#pragma unroll
        for (int bt = 0; bt < 32; bt++)
            dst[bt * 32] = bit2f((wbits >> bt) & 1u);
    }
    __syncthreads();
    int col = tid;
#pragma unroll
    for (int q = 0; q < 16; q++) acc2[q] = 0ull;
#pragma unroll 4
    for (int kk = 0; kk < 128; kk++) {
        float w = Wd[kk * DC + col];
        unsigned long long w2 = pack2(w, w);
        const ulonglong2* a4 = (const ulonglong2*)(sA + kk * 32);
#pragma unroll
        for (int q = 0; q < 8; q++) {
            ulonglong2 a = a4[q];
            FMA2(acc2[2 * q + 0], a.x, w2);
            FMA2(acc2[2 * q + 1], a.y, w2);
        }
    }
#pragma unroll
    for (int i = 0; i < 32; i++) {
        float lo, hi;
        unpack2(acc2[i >> 1], lo, hi);
        float a = (i & 1) ? hi : lo;
        int n = node0 + i;
        if (n < NN) g_adec[(size_t)n * DC + col] = a;
    }
}

// decoder: gather adec; LIF; accumulate y; last step writes sigmoid(mean) to out.
__global__ void k_dec(const int* __restrict__ ns, const int* __restrict__ nt,
                      const float* __restrict__ bd, const float* __restrict__ wrec,
                      int first, int last, float* __restrict__ out) {
    int wid = (blockIdx.x * blockDim.x + threadIdx.x) >> 5;
    int lane = threadIdx.x & 31;
    if (wid >= NL) return;
    int sn = ns[wid], tn = nt[wid];
    float a0s = g_adec[(size_t)sn * DC + lane];
    float a1s = g_adec[(size_t)sn * DC + lane + 32];
    float a0t = g_adec[(size_t)tn * DC + lane];
    float a1t = g_adec[(size_t)tn * DC + lane + 32];
    float b0 = bd[lane], b1 = bd[lane + 32];
    size_t is0 = (size_t)wid * DC + lane;
    size_t it0 = (size_t)(wid + NL) * DC + lane;
    float vv;
    vv = (first ? 0.f : g_vdec[is0] * 0.5f) + (a0s + b0);
    int zs0b = ((vv - 0.2f) >= 0.f); g_vdec[is0] = vv - (zs0b ? 0.2f : 0.f);
    vv = (first ? 0.f : g_vdec[is0 + 32] * 0.5f) + (a1s + b1);
    int zs1b = ((vv - 0.2f) >= 0.f); g_vdec[is0 + 32] = vv - (zs1b ? 0.2f : 0.f);
    vv = (first ? 0.f : g_vdec[it0] * 0.5f) + (a0t + b0);
    int zt0b = ((vv - 0.2f) >= 0.f); g_vdec[it0] = vv - (zt0b ? 0.2f : 0.f);
    vv = (first ? 0.f : g_vdec[it0 + 32] * 0.5f) + (a1t + b1);
    int zt1b = ((vv - 0.2f) >= 0.f); g_vdec[it0 + 32] = vv - (zt1b ? 0.2f : 0.f);

    float yp = ((zs0b && zt0b) ? wrec[lane] : 0.f) + ((zs1b && zt1b) ? wrec[lane + 32] : 0.f);
#pragma unroll
    for (int off = 16; off; off >>= 1) yp += __shfl_down_sync(FULLM, yp, off);
    if (lane == 0) {
        float ytot = first ? yp : (g_y[wid] + yp);
        if (last) {
            float m = ytot * 0.25f;
            float r;
            if (m >= 0.f) { float z = expf(-m); r = 1.f / (1.f + z); }
            else          { float z = expf(m);  r = z / (1.f + z); }
            out[wid] = r;
        } else {
            g_y[wid] = ytot;
        }
    }
}

// ---------------- host ------------------------------------------------------------
extern "C" void kernel_launch(void* const* d_in, const int* in_sizes, int n_in,
                              void* d_out, int out_size) {
    const float* x    = (const float*)d_in[0];
    const float* W1   = (const float*)d_in[1];
    const float* W2   = (const float*)d_in[2];
    const float* Wd   = (const float*)d_in[3];
    const float* bd   = (const float*)d_in[4];
    const float* wrec = (const float*)d_in[5];
    const float* ew   = (const float*)d_in[6];
    const int* esrc   = (const int*)d_in[7];
    const int* edst   = (const int*)d_in[8];
    const int* ns     = (const int*)d_in[9];
    const int* nt     = (const int*)d_in[10];
    float* out = (float*)d_out;

    void* p;
    float *v0z;
    unsigned *mHs0, *mZs0;
    int* deg;
    cudaGetSymbolAddress(&p, g_v0z);  v0z  = (float*)p;
    cudaGetSymbolAddress(&p, g_deg);  deg  = (int*)p;
    cudaGetSymbolAddress(&p, g_mHs0); mHs0 = (unsigned*)p;
    cudaGetSymbolAddress(&p, g_mZs0); mZs0 = (unsigned*)p;

    // second stream + events for chainA/chainB overlap (created per call; host-side only)
    cudaStream_t sA;
    cudaStreamCreateWithFlags(&sA, cudaStreamNonBlocking);
    cudaEvent_t evP2[4], evA[4], evEnd;
    for (int t = 0; t < 4; t++) {
        cudaEventCreateWithFlags(&evP2[t], cudaEventDisableTiming);
        cudaEventCreateWithFlags(&evA[t], cudaEventDisableTiming);
    }
    cudaEventCreateWithFlags(&evEnd, cudaEventDisableTiming);

    cudaMemsetAsync(deg, 0, sizeof(int) * NN);
    k_count<<<(NE + 255) / 256, 256>>>(edst);
    k_scan<<<1, 1024>>>();
    k_scatter<<<(NE + 255) / 256, 256>>>(edst);
    k_sortgather<<<(NN + 255) / 256, 256>>>(esrc, ew);

    const int GB = (NN + 31) / 32;
    for (unsigned t = 0; t < 4; t++) {
        int first = (t == 0);
        int last = (t == 3);
        unsigned kt0, kt1, k1_0, k1_1, k2_0, k2_1;
        tf2x32(0u, 42u, 0u, t, kt0, kt1);
        tf2x32(kt0, kt1, 0u, 0u, k1_0, k1_1);   // k1 = split(kt)[0]
        tf2x32(kt0, kt1, 0u, 1u, k2_0, k2_1);   // k2 = split(kt)[1]

        // chain B (stream 0): inp -> prop1 -> GEMM1
        k_inp<<<NN, 256>>>(x, k1_0, k1_1);
        k_prop1<<<(NN * 32) / 256, 256>>>(k2_0, k2_1);
        k_lifgemm<256, 256, 8, 8, 256><<<GB, 128>>>(mHs0, W1, v0z, mZs0, first);

        // prop2(t) needs gemm2dec(t-1) done (mHs1 overwrite)
        if (t > 0) cudaStreamWaitEvent(0, evA[t - 1], 0);
        k_prop2<<<(NN * 32) / 256, 256>>>(first);
        cudaEventRecord(evP2[t], 0);

        // chain A (stream sA): gemm2dec -> dec, concurrent with next step's chain B
        cudaStreamWaitEvent(sA, evP2[t], 0);
        k_gemm2dec<<<GB, 64, 0, sA>>>(W2, Wd, first);
        cudaEventRecord(evA[t], sA);
        k_dec<<<(NL * 32) / 256, 256, 0, sA>>>(ns, nt, bd, wrec, first, last, out);
    }
    // join chain A back into the origin stream before capture ends
    cudaEventRecord(evEnd, sA);
    cudaStreamWaitEvent(0, evEnd, 0);
}